// round 13
// baseline (speedup 1.0000x reference)
#include <cuda_runtime.h>
#include <cstdint>

#define T_STEPS 32
#define BATCH   8
#define NT      256
#define CIN_    1024
#define DCH     512
#define KC      64
#define PIX     196

typedef unsigned long long ull;

// ---------------- scratch (device globals; no allocations) ----------------
__device__ float g_xr[NT * DCH * PIX];       // (n, d, p)
__device__ float g_wxb[NT * KC * PIX];       // (n, k, p)
__device__ float g_h[2 * BATCH * KC * PIX];  // per-direction hidden state
__device__ float g_rh[2 * BATCH * KC * PIX];
__device__ float g_fwd[NT * KC * PIX];
__device__ float g_bwd[NT * KC * PIX];
__device__ float g_assign[NT * KC * PIX];
__device__ float g_asum[NT * KC];
__device__ float g_vlad[BATCH * KC * DCH];
__device__ unsigned int g_barrier[16];

static __device__ __forceinline__ float sigf(float v) { return 1.0f / (1.0f + expf(-v)); }

// packed fp32x2 helpers
static __device__ __forceinline__ ull pack2(float v) {
    ull r;
    unsigned u = __float_as_uint(v);
    asm("mov.b64 %0, {%1, %1};" : "=l"(r) : "r"(u));
    return r;
}
static __device__ __forceinline__ void ffma2(ull& d, ull a, ull b) {
    asm volatile("fma.rn.f32x2 %0, %1, %2, %0;" : "+l"(d) : "l"(a), "l"(b));
}
static __device__ __forceinline__ float lo32(ull u) { return __uint_as_float((unsigned)u); }
static __device__ __forceinline__ float hi32(ull u) { return __uint_as_float((unsigned)(u >> 32)); }

// ---------------- init: zero hidden states + vlad + barriers ----------------
__global__ void init_kernel()
{
    int i = blockIdx.x * 256 + threadIdx.x;
    if (i < 2 * BATCH * KC * PIX) g_h[i] = 0.0f;
    if (i < BATCH * KC * DCH)     g_vlad[i] = 0.0f;
    if (i < 16)                   g_barrier[i] = 0u;
}

// ---------------- 1x1 conv as double-buffered tiled SGEMM (f32x2, pre-dup B) ----------------
// out[(n*OC + d)*196 + p] = bias[d] + sum_c W[d][c] * X[(n*CIN + c)*196 + p]
// dynamic SMEM: As[2][BK][BM] floats | Bdup[2][BK][BN] ulls (B stored as duplicated f32x2)
template<int BM, int TM, int CIN, int OC>
__global__ void __launch_bounds__(256)
conv1x1_db(const float* __restrict__ X, const float* __restrict__ W,
           const float* __restrict__ bias, float* __restrict__ out)
{
    constexpr int BK = 16, BN = 128, TN = 8;
    constexpr int AL4 = (BM * BK) / (4 * 256);
    extern __shared__ __align__(16) char smraw[];
    float* As = (float*)smraw;                       // [2][BK][BM]
    ull*   Bd = (ull*)(smraw + 2 * BK * BM * 4);     // [2][BK][BN]
    __shared__ int cbase[BN], obase[BN];

    const int tid = threadIdx.x;
    if (tid < BN) {
        int jg = blockIdx.x * BN + tid;
        int n = jg / PIX, p = jg - n * PIX;
        cbase[tid] = n * CIN * PIX + p;
        obase[tid] = n * OC * PIX + p;
    }
    __syncthreads();

    const int m0 = blockIdx.y * BM;
    const int tx = tid & 15, ty = tid >> 4;
    const int bj = tid & 127, bk = tid >> 7;
    const int cb = cbase[bj];

    float4 areg[AL4];
    float  breg[8];

    auto loadA = [&](int k0) {
#pragma unroll
        for (int i = 0; i < AL4; i++) {
            int idx = tid + i * 256;
            int r = idx >> 2, c4 = idx & 3;
            areg[i] = *(const float4*)&W[(m0 + r) * CIN + k0 + c4 * 4];
        }
    };
    auto loadB = [&](int k0) {
#pragma unroll
        for (int i = 0; i < 8; i++) breg[i] = X[cb + (k0 + bk * 8 + i) * PIX];
    };
    auto storeA = [&](int buf) {
#pragma unroll
        for (int i = 0; i < AL4; i++) {
            int idx = tid + i * 256;
            int r = idx >> 2, c4 = idx & 3;
            As[(buf * BK + c4 * 4 + 0) * BM + r] = areg[i].x;
            As[(buf * BK + c4 * 4 + 1) * BM + r] = areg[i].y;
            As[(buf * BK + c4 * 4 + 2) * BM + r] = areg[i].z;
            As[(buf * BK + c4 * 4 + 3) * BM + r] = areg[i].w;
        }
    };
    auto storeB = [&](int buf) {
#pragma unroll
        for (int i = 0; i < 8; i++)
            Bd[(buf * BK + bk * 8 + i) * BN + bj] = pack2(breg[i]);
    };

    ull acc2[TM / 2][TN];
#pragma unroll
    for (int i = 0; i < TM / 2; i++)
#pragma unroll
        for (int j = 0; j < TN; j++) acc2[i][j] = 0ull;

    loadA(0); loadB(0);
    storeA(0); storeB(0);
    __syncthreads();

    int buf = 0;
    for (int k0 = 0; k0 < CIN; k0 += BK) {
        const bool more = (k0 + BK) < CIN;
        if (more) { loadA(k0 + BK); loadB(k0 + BK); }
#pragma unroll
        for (int kk = 0; kk < BK; kk++) {
            ull a2[TM / 2];
            const float* arow = As + (buf * BK + kk) * BM + ty * TM;
#pragma unroll
            for (int i = 0; i < TM / 2; i += 2) {
                // pairs (2i,2i+1),(2i+2,2i+3) live at float offset i*2
                ulonglong2 av = *(const ulonglong2*)(arow + i * 2);
                a2[i] = av.x; a2[i + 1] = av.y;
            }
            const ull* brow = Bd + (buf * BK + kk) * BN + tx * TN;
            ulonglong2 b01 = *(const ulonglong2*)&brow[0];
            ulonglong2 b23 = *(const ulonglong2*)&brow[2];
            ulonglong2 b45 = *(const ulonglong2*)&brow[4];
            ulonglong2 b67 = *(const ulonglong2*)&brow[6];
            ull bb[8] = { b01.x, b01.y, b23.x, b23.y, b45.x, b45.y, b67.x, b67.y };
#pragma unroll
            for (int i = 0; i < TM / 2; i++)
#pragma unroll
                for (int j = 0; j < TN; j++) ffma2(acc2[i][j], a2[i], bb[j]);
        }
        if (more) {
            storeA(buf ^ 1); storeB(buf ^ 1);
            __syncthreads();
            buf ^= 1;
        }
    }

#pragma unroll
    for (int i = 0; i < TM / 2; i++) {
        int d0 = m0 + ty * TM + 2 * i;
        float bv0 = bias[d0], bv1 = bias[d0 + 1];
#pragma unroll
        for (int j = 0; j < TN; j++) {
            ull u = acc2[i][j];
            int o = obase[tx * TN + j];
            out[o + d0 * PIX]       = lo32(u) + bv0;
            out[o + (d0 + 1) * PIX] = hi32(u) + bv1;
        }
    }
}

// ---------------- persistent bidirectional GRU (packed f32x2, pre-dup weights) ----------------
// 448 threads = 4 ci-quarters x 8 ko x 14 rows; each thread: one 14-px output row.
// Padded image: 16 rows x stride 18 per channel. Weights stored duplicated (f32x2).
#define GRU_THREADS 448
#define HS_STRIDE   288                    // 16 * 18
#define HS_FLOATS   (64 * HS_STRIDE)       // 18432
#define WS_ULLS     4608                   // 8 ko * 64 ci * 9 taps (as f32x2 pairs)
#define PQ_FLOATS   1568
#define GRU_SMEM_BYTES (HS_FLOATS * 4 + 3 * WS_ULLS * 8 + 6 * PQ_FLOATS * 4)  // 221952

__global__ void __launch_bounds__(GRU_THREADS, 1)
gru_persistent(const float* __restrict__ Uz, const float* __restrict__ Ur,
               const float* __restrict__ Uh)
{
    extern __shared__ __align__(16) float sm[];
    float* hs = sm;                                  // 64 channels, 16x18 padded
    ull*   wz = (ull*)(sm + HS_FLOATS);
    ull*   wr = wz + WS_ULLS;
    ull*   wh = wr + WS_ULLS;
    float* pz = (float*)(wh + WS_ULLS);              // 3*1568 partials (z / hcand)
    float* pr = pz + 3 * PQ_FLOATS;                  // 3*1568 partials (r)

    const int blk = blockIdx.x;
    const int grp = blk >> 3;              // dir*8 + b
    const int kg  = blk & 7;
    const int dir = grp >> 3;
    const int b   = grp & 7;
    const int tid = threadIdx.x;

    const int ko0 = kg * 8;
    for (int i = tid; i < WS_ULLS; i += GRU_THREADS) {
        wz[i] = pack2(Uz[ko0 * 576 + i]);
        wr[i] = pack2(Ur[ko0 * 576 + i]);
        wh[i] = pack2(Uh[ko0 * 576 + i]);
    }
    for (int i = tid; i < HS_FLOATS; i += GRU_THREADS) hs[i] = 0.0f;
    __syncthreads();

    const int q     = tid / 112;           // ci-quarter 0..3
    const int lt    = tid - q * 112;
    const int ko_l  = lt / 14;             // 0..7
    const int row   = lt - ko_l * 14;      // 0..13
    const int ko    = ko0 + ko_l;
    const int ci0   = q * 16;
    const int pidx  = ko_l * PIX + row * 14;

    float* hstate = g_h  + grp * KC * PIX;
    float* rhbuf  = g_rh + grp * KC * PIX;
    float* gdst   = (dir == 0) ? g_fwd : g_bwd;

    unsigned bar_target = 0;
    float zreg[14], hold[14];

    for (int s = 0; s < T_STEPS; s++) {
        const int t = dir ? (31 - s) : s;
        const int n = b * 32 + t;
        const float* wt = g_wxb + (n * KC + ko) * PIX + row * 14;

        // ---- stage h (interior only; halo stays 0) ----
        for (int i = tid; i < KC * PIX; i += GRU_THREADS) {
            int ci = i / PIX, p = i - ci * PIX;
            int y = p / 14, x = p - y * 14;
            hs[ci * HS_STRIDE + (y + 1) * 18 + (x + 1)] = __ldcg(&hstate[i]);
        }
        __syncthreads();

        // ---- phase A: z,r convs over this quarter's 16 channels ----
        ull az2[7], ar2[7];
#pragma unroll
        for (int j = 0; j < 7; j++) { az2[j] = 0ull; ar2[j] = 0ull; }
        {
            const ull* wzb = wz + ko_l * 576 + ci0 * 9;
            const ull* wrb = wr + ko_l * 576 + ci0 * 9;
            const float* hbase = hs + ci0 * HS_STRIDE + row * 18;
#pragma unroll 1
            for (int ci = 0; ci < 16; ci++) {
                const float* hrow = hbase + ci * HS_STRIDE;
                const ull* wz9 = wzb + ci * 9;
                const ull* wr9 = wrb + ci * 9;
#pragma unroll
                for (int r = 0; r < 3; r++) {
                    ull p[8];
#pragma unroll
                    for (int k = 0; k < 8; k++)
                        p[k] = *(const ull*)(hrow + r * 18 + 2 * k);
                    ull wa0 = wz9[3 * r + 0];
                    ull wa1 = wz9[3 * r + 1];
                    ull wa2 = wz9[3 * r + 2];
                    ull wb0 = wr9[3 * r + 0];
                    ull wb1 = wr9[3 * r + 1];
                    ull wb2 = wr9[3 * r + 2];
#pragma unroll
                    for (int j = 0; j < 7; j++) {
                        ull sft = (p[j] >> 32) | (p[j + 1] << 32);
                        ffma2(az2[j], p[j],     wa0);
                        ffma2(az2[j], sft,      wa1);
                        ffma2(az2[j], p[j + 1], wa2);
                        ffma2(ar2[j], p[j],     wb0);
                        ffma2(ar2[j], sft,      wb1);
                        ffma2(ar2[j], p[j + 1], wb2);
                    }
                }
            }
        }
        if (q > 0) {
            ull* pzq = (ull*)(pz + (q - 1) * PQ_FLOATS + pidx);
            ull* prq = (ull*)(pr + (q - 1) * PQ_FLOATS + pidx);
#pragma unroll
            for (int j = 0; j < 7; j++) { pzq[j] = az2[j]; prq[j] = ar2[j]; }
        }
        __syncthreads();
        if (q == 0) {
            float az[14], ar[14];
#pragma unroll
            for (int j = 0; j < 7; j++) {
                az[2 * j] = lo32(az2[j]); az[2 * j + 1] = hi32(az2[j]);
                ar[2 * j] = lo32(ar2[j]); ar[2 * j + 1] = hi32(ar2[j]);
            }
#pragma unroll
            for (int qq = 0; qq < 3; qq++) {
                const float* pzq = pz + qq * PQ_FLOATS + pidx;
                const float* prq = pr + qq * PQ_FLOATS + pidx;
#pragma unroll
                for (int px = 0; px < 14; px++) { az[px] += pzq[px]; ar[px] += prq[px]; }
            }
            const float* hko = hs + ko * HS_STRIDE + (row + 1) * 18 + 1;
            float* rdst = rhbuf + ko * PIX + row * 14;
#pragma unroll
            for (int px = 0; px < 14; px++) {
                float w = wt[px];
                float z = sigf(w + az[px]);
                float r = sigf(w + ar[px]);
                float h0 = hko[px];
                zreg[px] = z;
                hold[px] = h0;
                rdst[px] = r * h0;
            }
        }

        // ---- group barrier #1 ----
        __threadfence();
        __syncthreads();
        bar_target += 8;
        if (tid == 0) {
            atomicAdd(&g_barrier[grp], 1u);
            while (*((volatile unsigned int*)&g_barrier[grp]) < bar_target) __nanosleep(64);
            __threadfence();
        }
        __syncthreads();

        // ---- stage r*h ----
        for (int i = tid; i < KC * PIX; i += GRU_THREADS) {
            int ci = i / PIX, p = i - ci * PIX;
            int y = p / 14, x = p - y * 14;
            hs[ci * HS_STRIDE + (y + 1) * 18 + (x + 1)] = __ldcg(&rhbuf[i]);
        }
        __syncthreads();

        // ---- phase B: h-candidate conv ----
        ull ah2[7];
#pragma unroll
        for (int j = 0; j < 7; j++) ah2[j] = 0ull;
        {
            const ull* whb = wh + ko_l * 576 + ci0 * 9;
            const float* hbase = hs + ci0 * HS_STRIDE + row * 18;
#pragma unroll 1
            for (int ci = 0; ci < 16; ci++) {
                const float* hrow = hbase + ci * HS_STRIDE;
                const ull* w9 = whb + ci * 9;
#pragma unroll
                for (int r = 0; r < 3; r++) {
                    ull p[8];
#pragma unroll
                    for (int k = 0; k < 8; k++)
                        p[k] = *(const ull*)(hrow + r * 18 + 2 * k);
                    ull wa0 = w9[3 * r + 0];
                    ull wa1 = w9[3 * r + 1];
                    ull wa2 = w9[3 * r + 2];
#pragma unroll
                    for (int j = 0; j < 7; j++) {
                        ull sft = (p[j] >> 32) | (p[j + 1] << 32);
                        ffma2(ah2[j], p[j],     wa0);
                        ffma2(ah2[j], sft,      wa1);
                        ffma2(ah2[j], p[j + 1], wa2);
                    }
                }
            }
        }
        if (q > 0) {
            ull* pzq = (ull*)(pz + (q - 1) * PQ_FLOATS + pidx);
#pragma unroll
            for (int j = 0; j < 7; j++) pzq[j] = ah2[j];
        }
        __syncthreads();
        if (q == 0) {
            float ah[14];
#pragma unroll
            for (int j = 0; j < 7; j++) {
                ah[2 * j] = lo32(ah2[j]); ah[2 * j + 1] = hi32(ah2[j]);
            }
#pragma unroll
            for (int qq = 0; qq < 3; qq++) {
                const float* pzq = pz + qq * PQ_FLOATS + pidx;
#pragma unroll
                for (int px = 0; px < 14; px++) ah[px] += pzq[px];
            }
            float* hdst = hstate + ko * PIX + row * 14;
            float* fdst = gdst + (n * KC + ko) * PIX + row * 14;
#pragma unroll
            for (int px = 0; px < 14; px++) {
                float hh = tanhf(wt[px] + ah[px]);
                float z  = zreg[px];
                float hn = (1.0f - z) * hh + z * hold[px];
                hdst[px] = hn;
                fdst[px] = hn;
            }
        }

        // ---- group barrier #2 ----
        __threadfence();
        __syncthreads();
        bar_target += 8;
        if (tid == 0) {
            atomicAdd(&g_barrier[grp], 1u);
            while (*((volatile unsigned int*)&g_barrier[grp]) < bar_target) __nanosleep(64);
            __threadfence();
        }
        __syncthreads();
    }
}

// ---------------- softmax over K per pixel (single exp pass via SMEM) ----------------
// dynamic smem: se[64][224] floats = 57344 B
__global__ void softmax_kernel()
{
    extern __shared__ float se[];
    const int n = blockIdx.x;
    const int p = threadIdx.x;   // 224 threads, 196 active
    const bool act = p < PIX;
    __shared__ float asum_s[KC];
    if (p < KC) asum_s[p] = 0.0f;
    __syncthreads();

    const float* f  = g_fwd + n * KC * PIX + p;
    const float* bd = g_bwd + n * KC * PIX + p;
    float m = -1e30f;
    if (act) {
        for (int k = 0; k < KC; k++) {
            float v = f[k * PIX] + bd[k * PIX];
            se[k * 224 + p] = v;
            m = fmaxf(m, v);
        }
    }
    float ssum = 0.0f;
    if (act) {
        for (int k = 0; k < KC; k++) {
            float e = expf(se[k * 224 + p] - m);
            se[k * 224 + p] = e;
            ssum += e;
        }
    }
    const float inv = act ? (1.0f / ssum) : 0.0f;
    float* A = g_assign + n * KC * PIX + p;
    for (int k = 0; k < KC; k++) {
        float e = act ? se[k * 224 + p] * inv : 0.0f;
        if (act) A[k * PIX] = e;
        float es = e;
#pragma unroll
        for (int off = 16; off; off >>= 1) es += __shfl_down_sync(0xffffffffu, es, off);
        if ((p & 31) == 0) atomicAdd(&asum_s[k], es);
    }
    __syncthreads();
    if (p < KC) g_asum[n * KC + p] = asum_s[p];
}

// ---------------- VLAD einsum: vlad[b,k,d] += sum_{t,p} assign * xr ----------------
__global__ void vlad_gemm_kernel()
{
    __shared__ float As[14][65];
    __shared__ float Bs[14][65];
    const int b = blockIdx.y, d0 = blockIdx.x * 64, ch = blockIdx.z;
    const int tid = threadIdx.x;
    const int tx = tid & 15, ty = tid >> 4;

    float acc[4][4];
#pragma unroll
    for (int i = 0; i < 4; i++)
#pragma unroll
        for (int j = 0; j < 4; j++) acc[i][j] = 0.0f;

    for (int f = 0; f < 4; f++) {
        int n = b * 32 + ch * 4 + f;
        const float* Ap = g_assign + n * KC * PIX;
        const float* Xp = g_xr + (size_t)n * DCH * PIX;
        for (int p0 = 0; p0 < PIX; p0 += 14) {
            for (int i = tid; i < 896; i += 256) {
                int r = i / 14, pp = i - r * 14;
                As[pp][r] = Ap[r * PIX + p0 + pp];
                Bs[pp][r] = Xp[(d0 + r) * PIX + p0 + pp];
            }
            __syncthreads();
#pragma unroll
            for (int pp = 0; pp < 14; pp++) {
                float a[4], x[4];
#pragma unroll
                for (int i = 0; i < 4; i++) a[i] = As[pp][ty * 4 + i];
#pragma unroll
                for (int j = 0; j < 4; j++) x[j] = Bs[pp][tx * 4 + j];
#pragma unroll
                for (int i = 0; i < 4; i++)
#pragma unroll
                    for (int j = 0; j < 4; j++) acc[i][j] += a[i] * x[j];
            }
            __syncthreads();
        }
    }
#pragma unroll
    for (int i = 0; i < 4; i++)
#pragma unroll
        for (int j = 0; j < 4; j++)
            atomicAdd(&g_vlad[(b * KC + ty * 4 + i) * DCH + d0 + tx * 4 + j], acc[i][j]);
}

// ---------------- subtract a-term + intra-row L2 normalize ----------------
__global__ void rownorm_kernel(const float* __restrict__ centers, float* __restrict__ out)
{
    const int k = blockIdx.x, b = blockIdx.y;
    const int tid = threadIdx.x;  // 128
    __shared__ float sred[128];
    __shared__ float s_sh;

    if (tid < 32) {
        float s = g_asum[(b * 32 + tid) * KC + k];
#pragma unroll
        for (int off = 16; off; off >>= 1) s += __shfl_down_sync(0xffffffffu, s, off);
        if (tid == 0) s_sh = s;
    }
    __syncthreads();
    const float s = s_sh;

    float v[4];
    float ssq = 0.0f;
#pragma unroll
    for (int j = 0; j < 4; j++) {
        int d = j * 128 + tid;
        v[j] = g_vlad[(b * KC + k) * DCH + d] - s * centers[k * DCH + d];
        ssq += v[j] * v[j];
    }
    sred[tid] = ssq;
    __syncthreads();
    for (int off = 64; off; off >>= 1) {
        if (tid < off) sred[tid] += sred[tid + off];
        __syncthreads();
    }
    const float scale = 1.0f / fmaxf(sqrtf(sred[0]), 1e-12f);
#pragma unroll
    for (int j = 0; j < 4; j++)
        out[b * KC * DCH + k * DCH + j * 128 + tid] = v[j] * scale;
}

// ---------------- final per-batch L2 normalize ----------------
__global__ void bnorm_kernel(float* __restrict__ out)
{
    const int b = blockIdx.x;
    const int tid = threadIdx.x; // 256
    __shared__ float sred[256];
    float* o = out + b * KC * DCH;
    float ssq = 0.0f;
    for (int i = tid; i < KC * DCH; i += 256) { float v = o[i]; ssq += v * v; }
    sred[tid] = ssq;
    __syncthreads();
    for (int off = 128; off; off >>= 1) {
        if (tid < off) sred[tid] += sred[tid + off];
        __syncthreads();
    }
    const float scale = 1.0f / fmaxf(sqrtf(sred[0]), 1e-12f);
    for (int i = tid; i < KC * DCH; i += 256) o[i] *= scale;
}

// ---------------- host launcher ----------------
extern "C" void kernel_launch(void* const* d_in, const int* in_sizes, int n_in,
                              void* d_out, int out_size)
{
    const float* x       = (const float*)d_in[0];
    const float* redu_w  = (const float*)d_in[1];
    const float* redu_b  = (const float*)d_in[2];
    const float* share_w = (const float*)d_in[3];
    const float* share_b = (const float*)d_in[4];
    const float* U_z     = (const float*)d_in[5];
    const float* U_r     = (const float*)d_in[6];
    const float* U_h     = (const float*)d_in[7];
    const float* centers = (const float*)d_in[8];
    float* out = (float*)d_out;

    cudaFuncSetAttribute(gru_persistent, cudaFuncAttributeMaxDynamicSharedMemorySize, GRU_SMEM_BYTES);
    cudaFuncSetAttribute(softmax_kernel, cudaFuncAttributeMaxDynamicSharedMemorySize, 57344);

    const int C1_SM = 2 * 16 * 128 * 4 + 2 * 16 * 128 * 8;  // 49152
    const int C2_SM = 2 * 16 * 64 * 4 + 2 * 16 * 128 * 8;   // 40960
    cudaFuncSetAttribute((conv1x1_db<128, 8, CIN_, DCH>),
                         cudaFuncAttributeMaxDynamicSharedMemorySize, C1_SM);
    cudaFuncSetAttribute((conv1x1_db<64, 4, DCH, KC>),
                         cudaFuncAttributeMaxDynamicSharedMemorySize, C2_SM);

    void* xr_p;  cudaGetSymbolAddress(&xr_p,  g_xr);
    void* wxb_p; cudaGetSymbolAddress(&wxb_p, g_wxb);

    init_kernel<<<1024, 256>>>();

    // xr = 1x1 reduce conv + bias : GEMM (512 x 1024) @ (1024 x 50176)
    conv1x1_db<128, 8, CIN_, DCH>
        <<<dim3(50176 / 128, DCH / 128), 256, C1_SM>>>(x, redu_w, redu_b, (float*)xr_p);

    // wxb = 1x1 share conv + bias : GEMM (64 x 512) @ (512 x 50176)
    conv1x1_db<64, 4, DCH, KC>
        <<<dim3(50176 / 128, 1), 256, C2_SM>>>((const float*)xr_p, share_w, share_b, (float*)wxb_p);

    // persistent bidirectional GRU (packed f32x2, 448 threads, pre-dup weights)
    gru_persistent<<<128, GRU_THREADS, GRU_SMEM_BYTES>>>(U_z, U_r, U_h);

    softmax_kernel<<<NT, 224, 57344>>>();
    vlad_gemm_kernel<<<dim3(8, BATCH, 8), 256>>>();
    rownorm_kernel<<<dim3(KC, BATCH), 128>>>(centers, out);
    bnorm_kernel<<<BATCH, 256>>>(out);
}

// round 15
// speedup vs baseline: 1.9432x; 1.9432x over previous
#include <cuda_runtime.h>
#include <cstdint>

#define T_STEPS 32
#define BATCH   8
#define NT      256
#define CIN_    1024
#define DCH     512
#define KC      64
#define PIX     196

typedef unsigned long long ull;

// ---------------- scratch (device globals; no allocations) ----------------
__device__ float g_xr[NT * DCH * PIX];       // (n, d, p)
__device__ float g_wxb[NT * KC * PIX];       // (n, k, p)
__device__ float g_h[2 * BATCH * KC * PIX];  // per-direction hidden state
__device__ float g_rh[2 * BATCH * KC * PIX];
__device__ float g_fwd[NT * KC * PIX];
__device__ float g_bwd[NT * KC * PIX];
__device__ float g_assign[NT * KC * PIX];
__device__ float g_asum[NT * KC];
__device__ float g_vlad[BATCH * KC * DCH];
__device__ unsigned int g_barrier[16];

static __device__ __forceinline__ float sigf(float v) { return 1.0f / (1.0f + expf(-v)); }

// packed fp32x2 helpers
static __device__ __forceinline__ ull pack2(float v) {
    ull r;
    unsigned u = __float_as_uint(v);
    asm("mov.b64 %0, {%1, %1};" : "=l"(r) : "r"(u));
    return r;
}
static __device__ __forceinline__ void ffma2(ull& d, ull a, ull b) {
    asm volatile("fma.rn.f32x2 %0, %1, %2, %0;" : "+l"(d) : "l"(a), "l"(b));
}
static __device__ __forceinline__ float lo32(ull u) { return __uint_as_float((unsigned)u); }
static __device__ __forceinline__ float hi32(ull u) { return __uint_as_float((unsigned)(u >> 32)); }

// ---------------- init: zero hidden states + vlad + barriers ----------------
__global__ void init_kernel()
{
    int i = blockIdx.x * 256 + threadIdx.x;
    if (i < 2 * BATCH * KC * PIX) g_h[i] = 0.0f;
    if (i < BATCH * KC * DCH)     g_vlad[i] = 0.0f;
    if (i < 16)                   g_barrier[i] = 0u;
}

// ---------------- 1x1 conv as double-buffered tiled SGEMM (f32x2 FMAs) — R10 baseline ----------------
// out[(n*OC + d)*196 + p] = bias[d] + sum_c W[d][c] * X[(n*CIN + c)*196 + p]
template<int BM, int TM, int CIN, int OC>
__global__ void __launch_bounds__(256)
conv1x1_db(const float* __restrict__ X, const float* __restrict__ W,
           const float* __restrict__ bias, float* __restrict__ out)
{
    constexpr int BK = 16, BN = 128, TN = 8;
    constexpr int AL4 = (BM * BK) / (4 * 256);
    __shared__ __align__(16) float As[2][BK][BM];
    __shared__ __align__(16) float Bs[2][BK][BN];
    __shared__ int cbase[BN], obase[BN];

    const int tid = threadIdx.x;
    if (tid < BN) {
        int jg = blockIdx.x * BN + tid;
        int n = jg / PIX, p = jg - n * PIX;
        cbase[tid] = n * CIN * PIX + p;
        obase[tid] = n * OC * PIX + p;
    }
    __syncthreads();

    const int m0 = blockIdx.y * BM;
    const int tx = tid & 15, ty = tid >> 4;
    const int bj = tid & 127, bk = tid >> 7;
    const int cb = cbase[bj];

    float4 areg[AL4];
    float  breg[8];

    auto loadA = [&](int k0) {
#pragma unroll
        for (int i = 0; i < AL4; i++) {
            int idx = tid + i * 256;
            int r = idx >> 2, c4 = idx & 3;
            areg[i] = *(const float4*)&W[(m0 + r) * CIN + k0 + c4 * 4];
        }
    };
    auto loadB = [&](int k0) {
#pragma unroll
        for (int i = 0; i < 8; i++) breg[i] = X[cb + (k0 + bk * 8 + i) * PIX];
    };
    auto storeA = [&](int buf) {
#pragma unroll
        for (int i = 0; i < AL4; i++) {
            int idx = tid + i * 256;
            int r = idx >> 2, c4 = idx & 3;
            As[buf][c4 * 4 + 0][r] = areg[i].x;
            As[buf][c4 * 4 + 1][r] = areg[i].y;
            As[buf][c4 * 4 + 2][r] = areg[i].z;
            As[buf][c4 * 4 + 3][r] = areg[i].w;
        }
    };
    auto storeB = [&](int buf) {
#pragma unroll
        for (int i = 0; i < 8; i++) Bs[buf][bk * 8 + i][bj] = breg[i];
    };

    ull acc2[TM / 2][TN];
#pragma unroll
    for (int i = 0; i < TM / 2; i++)
#pragma unroll
        for (int j = 0; j < TN; j++) acc2[i][j] = 0ull;

    loadA(0); loadB(0);
    storeA(0); storeB(0);
    __syncthreads();

    int buf = 0;
    for (int k0 = 0; k0 < CIN; k0 += BK) {
        const bool more = (k0 + BK) < CIN;
        if (more) { loadA(k0 + BK); loadB(k0 + BK); }
#pragma unroll
        for (int kk = 0; kk < BK; kk++) {
            ull a2[TM / 2];
#pragma unroll
            for (int i = 0; i < TM / 2; i += 2) {
                ulonglong2 av = *(const ulonglong2*)&As[buf][kk][ty * TM + i * 2];
                a2[i] = av.x; a2[i + 1] = av.y;
            }
            float4 b0 = *(const float4*)&Bs[buf][kk][tx * TN];
            float4 b1 = *(const float4*)&Bs[buf][kk][tx * TN + 4];
            ull bb[8];
            bb[0] = pack2(b0.x); bb[1] = pack2(b0.y); bb[2] = pack2(b0.z); bb[3] = pack2(b0.w);
            bb[4] = pack2(b1.x); bb[5] = pack2(b1.y); bb[6] = pack2(b1.z); bb[7] = pack2(b1.w);
#pragma unroll
            for (int i = 0; i < TM / 2; i++)
#pragma unroll
                for (int j = 0; j < TN; j++) ffma2(acc2[i][j], a2[i], bb[j]);
        }
        if (more) {
            storeA(buf ^ 1); storeB(buf ^ 1);
            __syncthreads();
            buf ^= 1;
        }
    }

#pragma unroll
    for (int i = 0; i < TM / 2; i++) {
        int d0 = m0 + ty * TM + 2 * i;
        float bv0 = bias[d0], bv1 = bias[d0 + 1];
#pragma unroll
        for (int j = 0; j < TN; j++) {
            ull u = acc2[i][j];
            int o = obase[tx * TN + j];
            out[o + d0 * PIX]       = lo32(u) + bv0;
            out[o + (d0 + 1) * PIX] = hi32(u) + bv1;
        }
    }
}

// ---------------- persistent bidirectional GRU (packed f32x2) — R10 baseline ----------------
// 448 threads = 4 ci-quarters x 8 ko x 14 rows; each thread: one 14-px output row.
// Padded image: 16 rows x stride 18 per channel (halo cols 0,15; rows 0,15 zero).
#define GRU_THREADS 448
#define HS_STRIDE   288                    // 16 * 18
#define HS_FLOATS   (64 * HS_STRIDE)       // 18432
#define WS_FLOATS   4608
#define PQ_FLOATS   1568
#define GRU_SMEM_FLOATS (HS_FLOATS + 3 * WS_FLOATS + 6 * PQ_FLOATS)

__global__ void __launch_bounds__(GRU_THREADS, 1)
gru_persistent(const float* __restrict__ Uz, const float* __restrict__ Ur,
               const float* __restrict__ Uh)
{
    extern __shared__ float sm[];
    float* hs = sm;                        // 64 channels, 16x18 padded
    float* wz = sm + HS_FLOATS;
    float* wr = wz + WS_FLOATS;
    float* wh = wr + WS_FLOATS;
    float* pz = wh + WS_FLOATS;            // 3*1568 partials (z / hcand)
    float* pr = pz + 3 * PQ_FLOATS;        // 3*1568 partials (r)

    const int blk = blockIdx.x;
    const int grp = blk >> 3;              // dir*8 + b
    const int kg  = blk & 7;
    const int dir = grp >> 3;
    const int b   = grp & 7;
    const int tid = threadIdx.x;

    const int ko0 = kg * 8;
    for (int i = tid; i < WS_FLOATS; i += GRU_THREADS) {
        wz[i] = Uz[ko0 * 576 + i];
        wr[i] = Ur[ko0 * 576 + i];
        wh[i] = Uh[ko0 * 576 + i];
    }
    for (int i = tid; i < HS_FLOATS; i += GRU_THREADS) hs[i] = 0.0f;
    __syncthreads();

    const int q     = tid / 112;           // ci-quarter 0..3
    const int lt    = tid - q * 112;
    const int ko_l  = lt / 14;             // 0..7
    const int row   = lt - ko_l * 14;      // 0..13
    const int ko    = ko0 + ko_l;
    const int ci0   = q * 16;
    const int pidx  = ko_l * PIX + row * 14;

    float* hstate = g_h  + grp * KC * PIX;
    float* rhbuf  = g_rh + grp * KC * PIX;
    float* gdst   = (dir == 0) ? g_fwd : g_bwd;

    unsigned bar_target = 0;
    float zreg[14], hold[14];

    for (int s = 0; s < T_STEPS; s++) {
        const int t = dir ? (31 - s) : s;
        const int n = b * 32 + t;
        const float* wt = g_wxb + (n * KC + ko) * PIX + row * 14;

        // ---- stage h (interior only; halo stays 0) ----
        for (int i = tid; i < KC * PIX; i += GRU_THREADS) {
            int ci = i / PIX, p = i - ci * PIX;
            int y = p / 14, x = p - y * 14;
            hs[ci * HS_STRIDE + (y + 1) * 18 + (x + 1)] = __ldcg(&hstate[i]);
        }
        __syncthreads();

        // ---- phase A: z,r convs over this quarter's 16 channels (packed px pairs) ----
        ull az2[7], ar2[7];
#pragma unroll
        for (int j = 0; j < 7; j++) { az2[j] = 0ull; ar2[j] = 0ull; }
        {
            const float* wzb = wz + ko_l * 576 + ci0 * 9;
            const float* wrb = wr + ko_l * 576 + ci0 * 9;
            const float* hbase = hs + ci0 * HS_STRIDE + row * 18;
#pragma unroll 1
            for (int ci = 0; ci < 16; ci++) {
                const float* hrow = hbase + ci * HS_STRIDE;
                const float* wz9 = wzb + ci * 9;
                const float* wr9 = wrb + ci * 9;
#pragma unroll
                for (int r = 0; r < 3; r++) {
                    ull p[8];
#pragma unroll
                    for (int k = 0; k < 8; k++)
                        p[k] = *(const ull*)(hrow + r * 18 + 2 * k);
                    ull wa0 = pack2(wz9[3 * r + 0]);
                    ull wa1 = pack2(wz9[3 * r + 1]);
                    ull wa2 = pack2(wz9[3 * r + 2]);
                    ull wb0 = pack2(wr9[3 * r + 0]);
                    ull wb1 = pack2(wr9[3 * r + 1]);
                    ull wb2 = pack2(wr9[3 * r + 2]);
#pragma unroll
                    for (int j = 0; j < 7; j++) {
                        ull sft = (p[j] >> 32) | (p[j + 1] << 32);
                        ffma2(az2[j], p[j],     wa0);
                        ffma2(az2[j], sft,      wa1);
                        ffma2(az2[j], p[j + 1], wa2);
                        ffma2(ar2[j], p[j],     wb0);
                        ffma2(ar2[j], sft,      wb1);
                        ffma2(ar2[j], p[j + 1], wb2);
                    }
                }
            }
        }
        if (q > 0) {
            ull* pzq = (ull*)(pz + (q - 1) * PQ_FLOATS + pidx);
            ull* prq = (ull*)(pr + (q - 1) * PQ_FLOATS + pidx);
#pragma unroll
            for (int j = 0; j < 7; j++) { pzq[j] = az2[j]; prq[j] = ar2[j]; }
        }
        __syncthreads();
        if (q == 0) {
            float az[14], ar[14];
#pragma unroll
            for (int j = 0; j < 7; j++) {
                az[2 * j] = lo32(az2[j]); az[2 * j + 1] = hi32(az2[j]);
                ar[2 * j] = lo32(ar2[j]); ar[2 * j + 1] = hi32(ar2[j]);
            }
#pragma unroll
            for (int qq = 0; qq < 3; qq++) {
                const float* pzq = pz + qq * PQ_FLOATS + pidx;
                const float* prq = pr + qq * PQ_FLOATS + pidx;
#pragma unroll
                for (int px = 0; px < 14; px++) { az[px] += pzq[px]; ar[px] += prq[px]; }
            }
            const float* hko = hs + ko * HS_STRIDE + (row + 1) * 18 + 1;
            float* rdst = rhbuf + ko * PIX + row * 14;
#pragma unroll
            for (int px = 0; px < 14; px++) {
                float w = wt[px];
                float z = sigf(w + az[px]);
                float r = sigf(w + ar[px]);
                float h0 = hko[px];
                zreg[px] = z;
                hold[px] = h0;
                rdst[px] = r * h0;
            }
        }

        // ---- group barrier #1 ----
        __threadfence();
        __syncthreads();
        bar_target += 8;
        if (tid == 0) {
            atomicAdd(&g_barrier[grp], 1u);
            while (*((volatile unsigned int*)&g_barrier[grp]) < bar_target) __nanosleep(64);
            __threadfence();
        }
        __syncthreads();

        // ---- stage r*h ----
        for (int i = tid; i < KC * PIX; i += GRU_THREADS) {
            int ci = i / PIX, p = i - ci * PIX;
            int y = p / 14, x = p - y * 14;
            hs[ci * HS_STRIDE + (y + 1) * 18 + (x + 1)] = __ldcg(&rhbuf[i]);
        }
        __syncthreads();

        // ---- phase B: h-candidate conv ----
        ull ah2[7];
#pragma unroll
        for (int j = 0; j < 7; j++) ah2[j] = 0ull;
        {
            const float* whb = wh + ko_l * 576 + ci0 * 9;
            const float* hbase = hs + ci0 * HS_STRIDE + row * 18;
#pragma unroll 1
            for (int ci = 0; ci < 16; ci++) {
                const float* hrow = hbase + ci * HS_STRIDE;
                const float* w9 = whb + ci * 9;
#pragma unroll
                for (int r = 0; r < 3; r++) {
                    ull p[8];
#pragma unroll
                    for (int k = 0; k < 8; k++)
                        p[k] = *(const ull*)(hrow + r * 18 + 2 * k);
                    ull wa0 = pack2(w9[3 * r + 0]);
                    ull wa1 = pack2(w9[3 * r + 1]);
                    ull wa2 = pack2(w9[3 * r + 2]);
#pragma unroll
                    for (int j = 0; j < 7; j++) {
                        ull sft = (p[j] >> 32) | (p[j + 1] << 32);
                        ffma2(ah2[j], p[j],     wa0);
                        ffma2(ah2[j], sft,      wa1);
                        ffma2(ah2[j], p[j + 1], wa2);
                    }
                }
            }
        }
        if (q > 0) {
            ull* pzq = (ull*)(pz + (q - 1) * PQ_FLOATS + pidx);
#pragma unroll
            for (int j = 0; j < 7; j++) pzq[j] = ah2[j];
        }
        __syncthreads();
        if (q == 0) {
            float ah[14];
#pragma unroll
            for (int j = 0; j < 7; j++) {
                ah[2 * j] = lo32(ah2[j]); ah[2 * j + 1] = hi32(ah2[j]);
            }
#pragma unroll
            for (int qq = 0; qq < 3; qq++) {
                const float* pzq = pz + qq * PQ_FLOATS + pidx;
#pragma unroll
                for (int px = 0; px < 14; px++) ah[px] += pzq[px];
            }
            float* hdst = hstate + ko * PIX + row * 14;
            float* fdst = gdst + (n * KC + ko) * PIX + row * 14;
#pragma unroll
            for (int px = 0; px < 14; px++) {
                float hh = tanhf(wt[px] + ah[px]);
                float z  = zreg[px];
                float hn = (1.0f - z) * hh + z * hold[px];
                hdst[px] = hn;
                fdst[px] = hn;
            }
        }

        // ---- group barrier #2 ----
        __threadfence();
        __syncthreads();
        bar_target += 8;
        if (tid == 0) {
            atomicAdd(&g_barrier[grp], 1u);
            while (*((volatile unsigned int*)&g_barrier[grp]) < bar_target) __nanosleep(64);
            __threadfence();
        }
        __syncthreads();
    }
}

// ---------------- softmax over K per pixel (single exp pass via SMEM) ----------------
// dynamic smem: se[64][224] floats = 57344 B
__global__ void softmax_kernel()
{
    extern __shared__ float se[];
    const int n = blockIdx.x;
    const int p = threadIdx.x;   // 224 threads, 196 active
    const bool act = p < PIX;
    __shared__ float asum_s[KC];
    if (p < KC) asum_s[p] = 0.0f;
    __syncthreads();

    const float* f  = g_fwd + n * KC * PIX + p;
    const float* bd = g_bwd + n * KC * PIX + p;
    float m = -1e30f;
    if (act) {
        for (int k = 0; k < KC; k++) {
            float v = f[k * PIX] + bd[k * PIX];
            se[k * 224 + p] = v;
            m = fmaxf(m, v);
        }
    }
    float ssum = 0.0f;
    if (act) {
        for (int k = 0; k < KC; k++) {
            float e = expf(se[k * 224 + p] - m);
            se[k * 224 + p] = e;
            ssum += e;
        }
    }
    const float inv = act ? (1.0f / ssum) : 0.0f;
    float* A = g_assign + n * KC * PIX + p;
    for (int k = 0; k < KC; k++) {
        float e = act ? se[k * 224 + p] * inv : 0.0f;
        if (act) A[k * PIX] = e;
        float es = e;
#pragma unroll
        for (int off = 16; off; off >>= 1) es += __shfl_down_sync(0xffffffffu, es, off);
        if ((p & 31) == 0) atomicAdd(&asum_s[k], es);
    }
    __syncthreads();
    if (p < KC) g_asum[n * KC + p] = asum_s[p];
}

// ---------------- VLAD einsum: vlad[b,k,d] += sum_{t,p} assign * xr ----------------
__global__ void vlad_gemm_kernel()
{
    __shared__ float As[14][65];
    __shared__ float Bs[14][65];
    const int b = blockIdx.y, d0 = blockIdx.x * 64, ch = blockIdx.z;
    const int tid = threadIdx.x;
    const int tx = tid & 15, ty = tid >> 4;

    float acc[4][4];
#pragma unroll
    for (int i = 0; i < 4; i++)
#pragma unroll
        for (int j = 0; j < 4; j++) acc[i][j] = 0.0f;

    for (int f = 0; f < 4; f++) {
        int n = b * 32 + ch * 4 + f;
        const float* Ap = g_assign + n * KC * PIX;
        const float* Xp = g_xr + (size_t)n * DCH * PIX;
        for (int p0 = 0; p0 < PIX; p0 += 14) {
            for (int i = tid; i < 896; i += 256) {
                int r = i / 14, pp = i - r * 14;
                As[pp][r] = Ap[r * PIX + p0 + pp];
                Bs[pp][r] = Xp[(d0 + r) * PIX + p0 + pp];
            }
            __syncthreads();
#pragma unroll
            for (int pp = 0; pp < 14; pp++) {
                float a[4], x[4];
#pragma unroll
                for (int i = 0; i < 4; i++) a[i] = As[pp][ty * 4 + i];
#pragma unroll
                for (int j = 0; j < 4; j++) x[j] = Bs[pp][tx * 4 + j];
#pragma unroll
                for (int i = 0; i < 4; i++)
#pragma unroll
                    for (int j = 0; j < 4; j++) acc[i][j] += a[i] * x[j];
            }
            __syncthreads();
        }
    }
#pragma unroll
    for (int i = 0; i < 4; i++)
#pragma unroll
        for (int j = 0; j < 4; j++)
            atomicAdd(&g_vlad[(b * KC + ty * 4 + i) * DCH + d0 + tx * 4 + j], acc[i][j]);
}

// ---------------- subtract a-term + intra-row L2 normalize ----------------
__global__ void rownorm_kernel(const float* __restrict__ centers, float* __restrict__ out)
{
    const int k = blockIdx.x, b = blockIdx.y;
    const int tid = threadIdx.x;  // 128
    __shared__ float sred[128];
    __shared__ float s_sh;

    if (tid < 32) {
        float s = g_asum[(b * 32 + tid) * KC + k];
#pragma unroll
        for (int off = 16; off; off >>= 1) s += __shfl_down_sync(0xffffffffu, s, off);
        if (tid == 0) s_sh = s;
    }
    __syncthreads();
    const float s = s_sh;

    float v[4];
    float ssq = 0.0f;
#pragma unroll
    for (int j = 0; j < 4; j++) {
        int d = j * 128 + tid;
        v[j] = g_vlad[(b * KC + k) * DCH + d] - s * centers[k * DCH + d];
        ssq += v[j] * v[j];
    }
    sred[tid] = ssq;
    __syncthreads();
    for (int off = 64; off; off >>= 1) {
        if (tid < off) sred[tid] += sred[tid + off];
        __syncthreads();
    }
    const float scale = 1.0f / fmaxf(sqrtf(sred[0]), 1e-12f);
#pragma unroll
    for (int j = 0; j < 4; j++)
        out[b * KC * DCH + k * DCH + j * 128 + tid] = v[j] * scale;
}

// ---------------- final per-batch L2 normalize ----------------
__global__ void bnorm_kernel(float* __restrict__ out)
{
    const int b = blockIdx.x;
    const int tid = threadIdx.x; // 256
    __shared__ float sred[256];
    float* o = out + b * KC * DCH;
    float ssq = 0.0f;
    for (int i = tid; i < KC * DCH; i += 256) { float v = o[i]; ssq += v * v; }
    sred[tid] = ssq;
    __syncthreads();
    for (int off = 128; off; off >>= 1) {
        if (tid < off) sred[tid] += sred[tid + off];
        __syncthreads();
    }
    const float scale = 1.0f / fmaxf(sqrtf(sred[0]), 1e-12f);
    for (int i = tid; i < KC * DCH; i += 256) o[i] *= scale;
}

// ---------------- host launcher ----------------
extern "C" void kernel_launch(void* const* d_in, const int* in_sizes, int n_in,
                              void* d_out, int out_size)
{
    const float* x       = (const float*)d_in[0];
    const float* redu_w  = (const float*)d_in[1];
    const float* redu_b  = (const float*)d_in[2];
    const float* share_w = (const float*)d_in[3];
    const float* share_b = (const float*)d_in[4];
    const float* U_z     = (const float*)d_in[5];
    const float* U_r     = (const float*)d_in[6];
    const float* U_h     = (const float*)d_in[7];
    const float* centers = (const float*)d_in[8];
    float* out = (float*)d_out;

    const int GRU_SMEM = GRU_SMEM_FLOATS * 4;   // ~162.8 KB
    cudaFuncSetAttribute(gru_persistent, cudaFuncAttributeMaxDynamicSharedMemorySize, GRU_SMEM);
    cudaFuncSetAttribute(softmax_kernel, cudaFuncAttributeMaxDynamicSharedMemorySize, 57344);

    void* xr_p;  cudaGetSymbolAddress(&xr_p,  g_xr);
    void* wxb_p; cudaGetSymbolAddress(&wxb_p, g_wxb);

    init_kernel<<<1024, 256>>>();

    // xr = 1x1 reduce conv + bias : GEMM (512 x 1024) @ (1024 x 50176)
    conv1x1_db<128, 8, CIN_, DCH>
        <<<dim3(50176 / 128, DCH / 128), 256>>>(x, redu_w, redu_b, (float*)xr_p);

    // wxb = 1x1 share conv + bias : GEMM (64 x 512) @ (512 x 50176)
    conv1x1_db<64, 4, DCH, KC>
        <<<dim3(50176 / 128, 1), 256>>>((const float*)xr_p, share_w, share_b, (float*)wxb_p);

    // persistent bidirectional GRU (packed f32x2, 448 threads)
    gru_persistent<<<128, GRU_THREADS, GRU_SMEM>>>(U_z, U_r, U_h);

    softmax_kernel<<<NT, 224, 57344>>>();
    vlad_gemm_kernel<<<dim3(8, BATCH, 8), 256>>>();
    rownorm_kernel<<<dim3(KC, BATCH), 128>>>(centers, out);
    bnorm_kernel<<<BATCH, 256>>>(out);
}